// round 11
// baseline (speedup 1.0000x reference)
#include <cuda_runtime.h>

#define L   8192
#define CH  512
#define N   64
#define NC  128
#define T   64    // L / NC
typedef unsigned long long ull;

// ---- scratch / constants (no allocation allowed) ----
__device__ float d_Abar[N];
__device__ float d_CB[N];
__device__ float d_AbarT[N];
__device__ float d_W[T * N];                    // W[i][n] = CB[n]*Abar[n]^(i+1)
__device__ ull d_S[(size_t)NC * (N / 2) * CH];  // [j][n2][c]  lane-coalesced
__device__ ull d_H[(size_t)NC * (N / 2) * CH];  // carry INTO chunk j, same layout

// ---- packed f32x2 helpers ----
__device__ __forceinline__ ull pack2(float lo, float hi) {
    ull r; asm("mov.b64 %0, {%1, %2};" : "=l"(r) : "f"(lo), "f"(hi)); return r;
}
__device__ __forceinline__ void unpack2(ull v, float& lo, float& hi) {
    asm("mov.b64 {%0, %1}, %2;" : "=f"(lo), "=f"(hi) : "l"(v));
}
__device__ __forceinline__ ull fma2(ull a, ull b, ull c) {
    ull r; asm("fma.rn.f32x2 %0, %1, %2, %3;" : "=l"(r) : "l"(a), "l"(b), "l"(c)); return r;
}
__device__ __forceinline__ ull add2(ull a, ull b) {
    ull r; asm("add.rn.f32x2 %0, %1, %2;" : "=l"(r) : "l"(a), "l"(b)); return r;
}

// ---- pass 0: coefficients + W matrix ----
__global__ void precompute_kernel(const float* __restrict__ logA,
                                  const float* __restrict__ B,
                                  const float* __restrict__ C) {
    __shared__ float sA[N], sCB[N];
    const float dt = 1.0f / 4096.0f;
    int tid = threadIdx.x;
    if (tid < N) {
        float A    = -expf(logA[tid]);
        float Abar = expf(A * dt);
        float Bbar = (Abar - 1.0f) * B[tid] / A;
        float CB   = C[tid] * Bbar;
        d_Abar[tid]  = Abar;
        d_CB[tid]    = CB;
        d_AbarT[tid] = expf(A * dt * (float)T);
        sA[tid] = A; sCB[tid] = CB;
    }
    __syncthreads();
    for (int idx = tid; idx < T * N; idx += blockDim.x) {
        int i = idx >> 6, n = idx & 63;
        d_W[idx] = sCB[n] * expf(sA[n] * (dt * (float)(i + 1)));
    }
}

// ---- K1: local scan (zero init) + dot -> y_local, store end state S ----
// block 64 = 32 channels x 2 halves (32 states each). 1 shfl per step.
__global__ void __launch_bounds__(64) scan_y_kernel(const float* __restrict__ x,
                                                    float* __restrict__ y) {
    __shared__ float2 xs2[T][32];      // duplicated x: {v,v}, 16KB
    const int j   = blockIdx.x;
    const int cg  = blockIdx.y;
    const int tid = threadIdx.x;

    for (int i = tid; i < T * 8; i += 64) {
        int r = i >> 3, q = i & 7;
        float4 v = *(const float4*)(x + (size_t)(j * T + r) * CH + cg * 32 + q * 4);
        float4* dst = (float4*)&xs2[r][q * 4];
        dst[0] = make_float4(v.x, v.x, v.y, v.y);
        dst[1] = make_float4(v.z, v.z, v.w, v.w);
    }
    __syncthreads();

    const int chl = tid >> 1;          // 0..31, lane pairs share a channel
    const int qs  = tid & 1;           // which 32 states
    const int c   = cg * 32 + chl;

    ull a2[16], cb2[16], g2[16];
    const float2* Ab = (const float2*)d_Abar;
    const float2* Cb = (const float2*)d_CB;
#pragma unroll
    for (int k = 0; k < 16; k++) {
        float2 a  = Ab[qs * 16 + k];
        float2 cb = Cb[qs * 16 + k];
        a2[k]  = pack2(a.x, a.y);
        cb2[k] = pack2(cb.x, cb.y);
        g2[k]  = 0ULL;
    }

    const ull* xrow = (const ull*)&xs2[0][chl];
    float* yp = y + (size_t)j * T * CH + c;
#pragma unroll 2
    for (int t = 0; t < T; t++) {
        ull x2 = xrow[(size_t)t * 32];
#pragma unroll
        for (int k = 0; k < 16; k++) g2[k] = fma2(a2[k], g2[k], x2);

        ull acc0 = 0ULL, acc1 = 0ULL, acc2 = 0ULL, acc3 = 0ULL;
#pragma unroll
        for (int k = 0; k < 16; k += 4) {
            acc0 = fma2(cb2[k],     g2[k],     acc0);
            acc1 = fma2(cb2[k + 1], g2[k + 1], acc1);
            acc2 = fma2(cb2[k + 2], g2[k + 2], acc2);
            acc3 = fma2(cb2[k + 3], g2[k + 3], acc3);
        }
        float lo, hi;
        unpack2(add2(add2(acc0, acc1), add2(acc2, acc3)), lo, hi);
        float ypv = lo + hi;
        ypv += __shfl_xor_sync(0xffffffffu, ypv, 1);
        if (qs == 0) yp[(size_t)t * CH] = ypv;
    }

    // coalesced S store: [j][qs*16+k][c]
#pragma unroll
    for (int k = 0; k < 16; k++)
        d_S[((size_t)j * 32 + qs * 16 + k) * CH + c] = g2[k];
}

// ---- K2: sequential prefix over chunks (coalesced, f32x2) ----
__global__ void carry_kernel() {
    int idx = blockIdx.x * blockDim.x + threadIdx.x;   // 16384 threads
    if (idx >= CH * N / 2) return;
    int c  = idx & (CH - 1);
    int n2 = idx >> 9;
    float2 aTf = ((const float2*)d_AbarT)[n2];
    ull aT = pack2(aTf.x, aTf.y);
    ull carry = 0ULL;
#pragma unroll 8
    for (int j = 0; j < NC; j++) {
        size_t off = ((size_t)j * 32 + n2) * CH + c;
        ull s = d_S[off];
        d_H[off] = carry;
        carry = fma2(aT, carry, s);
    }
}

// ---- K3: correction  y[j*T+i][c] += sum_n W[i][n] * H[j][c][n] ----
// H in registers (32 ull), W broadcast from smem. Fully parallel.
__global__ void __launch_bounds__(64) corr_kernel(float* __restrict__ y) {
    __shared__ ull W2s[T * 32];        // 16KB
    const int j   = blockIdx.x;
    const int cg  = blockIdx.y;
    const int tid = threadIdx.x;

    const float2* Wg = (const float2*)d_W;
    for (int i = tid; i < T * 32; i += 64) {
        float2 w = Wg[i];
        W2s[i] = pack2(w.x, w.y);
    }
    __syncthreads();

    const int c = cg * 64 + tid;
    ull h[32];
#pragma unroll
    for (int k = 0; k < 32; k++)
        h[k] = d_H[((size_t)j * 32 + k) * CH + c];

    float* yp = y + (size_t)j * T * CH + c;
#pragma unroll 2
    for (int i = 0; i < T; i++) {
        const ull* wr = &W2s[i * 32];
        ull acc0 = 0ULL, acc1 = 0ULL, acc2 = 0ULL, acc3 = 0ULL;
#pragma unroll
        for (int k = 0; k < 32; k += 4) {
            acc0 = fma2(wr[k],     h[k],     acc0);
            acc1 = fma2(wr[k + 1], h[k + 1], acc1);
            acc2 = fma2(wr[k + 2], h[k + 2], acc2);
            acc3 = fma2(wr[k + 3], h[k + 3], acc3);
        }
        float lo, hi;
        unpack2(add2(add2(acc0, acc1), add2(acc2, acc3)), lo, hi);
        yp[(size_t)i * CH] += lo + hi;
    }
}

extern "C" void kernel_launch(void* const* d_in, const int* in_sizes, int n_in,
                              void* d_out, int out_size) {
    const float* x    = (const float*)d_in[0];
    const float* logA = (const float*)d_in[1];
    const float* B    = (const float*)d_in[2];
    const float* C    = (const float*)d_in[3];
    float* y = (float*)d_out;

    precompute_kernel<<<1, 256>>>(logA, B, C);
    scan_y_kernel<<<dim3(NC, CH / 32), 64>>>(x, y);
    carry_kernel<<<CH * N / 2 / 128, 128>>>();
    corr_kernel<<<dim3(NC, CH / 64), 64>>>(y);
}

// round 12
// speedup vs baseline: 1.0175x; 1.0175x over previous
#include <cuda_runtime.h>

#define L   8192
#define CH  512
#define N   64
#define NC  128
#define T   64    // L / NC
typedef unsigned long long ull;

// ---- scratch / constants (no allocation allowed) ----
__device__ float d_Abar[N];
__device__ float d_CB[N];
__device__ float d_AbarT[N];
__device__ float d_W[T * N];                    // W[i][n] = CB[n]*Abar[n]^(i+1)
__device__ ull d_S[(size_t)NC * (N / 2) * CH];  // [j][n2][c]  lane-coalesced
__device__ ull d_H[(size_t)NC * (N / 2) * CH];  // carry INTO chunk j, same layout

// ---- packed f32x2 helpers ----
__device__ __forceinline__ ull pack2(float lo, float hi) {
    ull r; asm("mov.b64 %0, {%1, %2};" : "=l"(r) : "f"(lo), "f"(hi)); return r;
}
__device__ __forceinline__ void unpack2(ull v, float& lo, float& hi) {
    asm("mov.b64 {%0, %1}, %2;" : "=f"(lo), "=f"(hi) : "l"(v));
}
__device__ __forceinline__ ull fma2(ull a, ull b, ull c) {
    ull r; asm("fma.rn.f32x2 %0, %1, %2, %3;" : "=l"(r) : "l"(a), "l"(b), "l"(c)); return r;
}
__device__ __forceinline__ ull add2(ull a, ull b) {
    ull r; asm("add.rn.f32x2 %0, %1, %2;" : "=l"(r) : "l"(a), "l"(b)); return r;
}

// ---- pass 0: coefficients + W matrix ----
__global__ void precompute_kernel(const float* __restrict__ logA,
                                  const float* __restrict__ B,
                                  const float* __restrict__ C) {
    __shared__ float sA[N], sCB[N];
    const float dt = 1.0f / 4096.0f;
    int tid = threadIdx.x;
    if (tid < N) {
        float A    = -expf(logA[tid]);
        float Abar = expf(A * dt);
        float Bbar = (Abar - 1.0f) * B[tid] / A;
        float CB   = C[tid] * Bbar;
        d_Abar[tid]  = Abar;
        d_CB[tid]    = CB;
        d_AbarT[tid] = expf(A * dt * (float)T);
        sA[tid] = A; sCB[tid] = CB;
    }
    __syncthreads();
    for (int idx = tid; idx < T * N; idx += blockDim.x) {
        int i = idx >> 6, n = idx & 63;
        d_W[idx] = sCB[n] * expf(sA[n] * (dt * (float)(i + 1)));
    }
}

// ---- K1: local scan (zero init) + dot -> y_local, store end state S ----
// block 64 = 32 channels x 2 halves (32 states each). 1 shfl per step.
__global__ void __launch_bounds__(64) scan_y_kernel(const float* __restrict__ x,
                                                    float* __restrict__ y) {
    __shared__ float2 xs2[T][32];      // duplicated x: {v,v}, 16KB
    const int j   = blockIdx.x;
    const int cg  = blockIdx.y;
    const int tid = threadIdx.x;

    for (int i = tid; i < T * 8; i += 64) {
        int r = i >> 3, q = i & 7;
        float4 v = *(const float4*)(x + (size_t)(j * T + r) * CH + cg * 32 + q * 4);
        float4* dst = (float4*)&xs2[r][q * 4];
        dst[0] = make_float4(v.x, v.x, v.y, v.y);
        dst[1] = make_float4(v.z, v.z, v.w, v.w);
    }
    __syncthreads();

    const int chl = tid >> 1;          // 0..31, lane pairs share a channel
    const int qs  = tid & 1;           // which 32 states
    const int c   = cg * 32 + chl;

    ull a2[16], cb2[16], g2[16];
    const float2* Ab = (const float2*)d_Abar;
    const float2* Cb = (const float2*)d_CB;
#pragma unroll
    for (int k = 0; k < 16; k++) {
        float2 a  = Ab[qs * 16 + k];
        float2 cb = Cb[qs * 16 + k];
        a2[k]  = pack2(a.x, a.y);
        cb2[k] = pack2(cb.x, cb.y);
        g2[k]  = 0ULL;
    }

    const ull* xrow = (const ull*)&xs2[0][chl];
    float* yp = y + (size_t)j * T * CH + c;
#pragma unroll 2
    for (int t = 0; t < T; t++) {
        ull x2 = xrow[(size_t)t * 32];
#pragma unroll
        for (int k = 0; k < 16; k++) g2[k] = fma2(a2[k], g2[k], x2);

        ull acc0 = 0ULL, acc1 = 0ULL, acc2 = 0ULL, acc3 = 0ULL;
#pragma unroll
        for (int k = 0; k < 16; k += 4) {
            acc0 = fma2(cb2[k],     g2[k],     acc0);
            acc1 = fma2(cb2[k + 1], g2[k + 1], acc1);
            acc2 = fma2(cb2[k + 2], g2[k + 2], acc2);
            acc3 = fma2(cb2[k + 3], g2[k + 3], acc3);
        }
        float lo, hi;
        unpack2(add2(add2(acc0, acc1), add2(acc2, acc3)), lo, hi);
        float ypv = lo + hi;
        ypv += __shfl_xor_sync(0xffffffffu, ypv, 1);
        if (qs == 0) yp[(size_t)t * CH] = ypv;
    }

    // coalesced S store: [j][qs*16+k][c]
#pragma unroll
    for (int k = 0; k < 16; k++)
        d_S[((size_t)j * 32 + qs * 16 + k) * CH + c] = g2[k];
}

// ---- K2: sequential prefix over chunks (coalesced, f32x2) ----
__global__ void carry_kernel() {
    int idx = blockIdx.x * blockDim.x + threadIdx.x;   // 16384 threads
    if (idx >= CH * N / 2) return;
    int c  = idx & (CH - 1);
    int n2 = idx >> 9;
    float2 aTf = ((const float2*)d_AbarT)[n2];
    ull aT = pack2(aTf.x, aTf.y);
    ull carry = 0ULL;
#pragma unroll 8
    for (int j = 0; j < NC; j++) {
        size_t off = ((size_t)j * 32 + n2) * CH + c;
        ull s = d_S[off];
        d_H[off] = carry;
        carry = fma2(aT, carry, s);
    }
}

// ---- K3: correction  y[j*T+i][c] += sum_n W[i][n] * H[j][c][n] ----
// H in registers (32 ull), W broadcast from smem. Fully parallel.
__global__ void __launch_bounds__(64) corr_kernel(float* __restrict__ y) {
    __shared__ ull W2s[T * 32];        // 16KB
    const int j   = blockIdx.x;
    const int cg  = blockIdx.y;
    const int tid = threadIdx.x;

    const float2* Wg = (const float2*)d_W;
    for (int i = tid; i < T * 32; i += 64) {
        float2 w = Wg[i];
        W2s[i] = pack2(w.x, w.y);
    }
    __syncthreads();

    const int c = cg * 64 + tid;
    ull h[32];
#pragma unroll
    for (int k = 0; k < 32; k++)
        h[k] = d_H[((size_t)j * 32 + k) * CH + c];

    float* yp = y + (size_t)j * T * CH + c;
#pragma unroll 2
    for (int i = 0; i < T; i++) {
        const ull* wr = &W2s[i * 32];
        ull acc0 = 0ULL, acc1 = 0ULL, acc2 = 0ULL, acc3 = 0ULL;
#pragma unroll
        for (int k = 0; k < 32; k += 4) {
            acc0 = fma2(wr[k],     h[k],     acc0);
            acc1 = fma2(wr[k + 1], h[k + 1], acc1);
            acc2 = fma2(wr[k + 2], h[k + 2], acc2);
            acc3 = fma2(wr[k + 3], h[k + 3], acc3);
        }
        float lo, hi;
        unpack2(add2(add2(acc0, acc1), add2(acc2, acc3)), lo, hi);
        yp[(size_t)i * CH] += lo + hi;
    }
}

extern "C" void kernel_launch(void* const* d_in, const int* in_sizes, int n_in,
                              void* d_out, int out_size) {
    const float* x    = (const float*)d_in[0];
    const float* logA = (const float*)d_in[1];
    const float* B    = (const float*)d_in[2];
    const float* C    = (const float*)d_in[3];
    float* y = (float*)d_out;

    precompute_kernel<<<1, 256>>>(logA, B, C);
    scan_y_kernel<<<dim3(NC, CH / 32), 64>>>(x, y);
    carry_kernel<<<CH * N / 2 / 128, 128>>>();
    corr_kernel<<<dim3(NC, CH / 64), 64>>>(y);
}

// round 13
// speedup vs baseline: 1.1355x; 1.1159x over previous
#include <cuda_runtime.h>

#define L   8192
#define CH  512
#define N   64
#define NC  128
#define T   64
typedef unsigned long long ull;

// ---- constants / scratch (no allocation allowed) ----
__device__ float d_A[N];                       // continuous A_n
__device__ float d_CB[N];                      // C_n * Bbar_n
__device__ float d_AbarT[N];                   // Abar_n^T
__device__ float d_K[T];                       // K[d] = sum_n CB_n Abar_n^d
__device__ float d_G1A[T * N];                 // [s][n] = Abar_n^(63-s)
__device__ float d_G2A[(T + N) * T];           // [k][i]: k<64 Toep, k>=64 W
__device__ ull   d_S[(size_t)NC * (N / 2) * CH];   // [j][n2][c] packed pairs
__device__ float d_Hf[(size_t)NC * N * CH];        // [j][n][c] planar carry-in

// ---- packed f32x2 helpers ----
__device__ __forceinline__ ull pack2(float lo, float hi) {
    ull r; asm("mov.b64 %0, {%1, %2};" : "=l"(r) : "f"(lo), "f"(hi)); return r;
}
__device__ __forceinline__ void unpack2(ull v, float& lo, float& hi) {
    asm("mov.b64 {%0, %1}, %2;" : "=f"(lo), "=f"(hi) : "l"(v));
}
__device__ __forceinline__ ull fma2(ull a, ull b, ull c) {
    ull r; asm("fma.rn.f32x2 %0, %1, %2, %3;" : "=l"(r) : "l"(a), "l"(b), "l"(c)); return r;
}

// ---- prep0: per-state params + Toeplitz kernel K[d] ----
__global__ void prep0_kernel(const float* __restrict__ logA,
                             const float* __restrict__ B,
                             const float* __restrict__ C) {
    __shared__ float sA[N], sCB[N], part[T][4];
    const float dt = 1.0f / 4096.0f;
    int tid = threadIdx.x;
    if (tid < N) {
        float A    = -expf(logA[tid]);
        float Abar = expf(A * dt);
        float Bbar = (Abar - 1.0f) * B[tid] / A;
        float cb   = C[tid] * Bbar;
        d_A[tid] = A;  sA[tid] = A;
        d_CB[tid] = cb; sCB[tid] = cb;
        d_AbarT[tid] = expf(A * dt * (float)T);
    }
    __syncthreads();
    int dpos = tid >> 2, p = tid & 3;
    float s = 0.f;
#pragma unroll
    for (int n = p * 16; n < p * 16 + 16; n++)
        s += sCB[n] * expf(sA[n] * dt * (float)dpos);
    part[dpos][p] = s;
    __syncthreads();
    if (tid < T)
        d_K[tid] = (part[tid][0] + part[tid][1]) + (part[tid][2] + part[tid][3]);
}

// ---- prep1: fill G1/G2 A-matrices (transposed [k][i] layout) ----
__global__ void prep1_kernel() {
    int idx = blockIdx.x * blockDim.x + threadIdx.x;
    const float dt = 1.0f / 4096.0f;
    if (idx < T * N) {                    // d_G1A[s][n] = Abar_n^(63-s)
        int s = idx >> 6, n = idx & 63;
        d_G1A[idx] = expf(d_A[n] * dt * (float)(63 - s));
    }
    int j = idx - T * N;
    if (j >= 0 && j < (T + N) * T) {      // d_G2A[k][i]
        int k = j >> 6, i = j & 63;
        float v;
        if (k < T) v = (i >= k) ? d_K[i - k] : 0.f;
        else {
            int n = k - T;
            v = d_CB[n] * expf(d_A[n] * dt * (float)(i + 1));
        }
        d_G2A[j] = v;
    }
}

// ---- G1: S_j = E @ X_j  (64n x 512c per chunk) ----
__global__ void __launch_bounds__(256) g1_kernel(const float* __restrict__ x) {
    __shared__ float As[32][64];    // 8KB
    __shared__ float Bs[32][128];   // 16KB
    const int j = blockIdx.x, cq = blockIdx.y, tid = threadIdx.x;
    const int ith = tid >> 5, cth = tid & 31;
    const int i0 = ith * 8;

    ull acc[4][4];
#pragma unroll
    for (int p = 0; p < 4; p++)
#pragma unroll
        for (int q = 0; q < 4; q++) acc[p][q] = 0ULL;

    for (int sl = 0; sl < 2; sl++) {
        {   // stage As (2048 f32)
            const float4* src = (const float4*)(d_G1A + sl * 32 * 64);
            float4* dst = (float4*)&As[0][0];
            dst[tid] = src[tid];
            dst[tid + 256] = src[tid + 256];
        }
#pragma unroll
        for (int u = 0; u < 4; u++) {   // stage Bs (32 rows x 128c)
            int e = tid + u * 256;
            int r = e >> 5, fc = e & 31;
            int kg = sl * 32 + r;
            ((float4*)&Bs[r][0])[fc] =
                *((const float4*)(x + ((size_t)(j * T + kg) * CH + cq * 128)) + fc);
        }
        __syncthreads();
#pragma unroll 8
        for (int r = 0; r < 32; r++) {
            float4 a0 = *(const float4*)&As[r][i0];
            float4 a1 = *(const float4*)&As[r][i0 + 4];
            ull a2[4] = { pack2(a0.x, a0.y), pack2(a0.z, a0.w),
                          pack2(a1.x, a1.y), pack2(a1.z, a1.w) };
            float b0 = Bs[r][cth], b1 = Bs[r][cth + 32],
                  b2v = Bs[r][cth + 64], b3 = Bs[r][cth + 96];
            ull bd[4] = { pack2(b0, b0), pack2(b1, b1),
                          pack2(b2v, b2v), pack2(b3, b3) };
#pragma unroll
            for (int p = 0; p < 4; p++)
#pragma unroll
                for (int q = 0; q < 4; q++)
                    acc[p][q] = fma2(a2[p], bd[q], acc[p][q]);
        }
        __syncthreads();
    }
    // store S (pairs (2n2, 2n2+1) in one ull)
    ull* Sp = d_S + (size_t)j * 32 * CH;
#pragma unroll
    for (int p = 0; p < 4; p++)
#pragma unroll
        for (int q = 0; q < 4; q++)
            Sp[(size_t)(i0 / 2 + p) * CH + cq * 128 + cth + 32 * q] = acc[p][q];
}

// ---- carry: H_{j+1} = AbarT (.) H_j + S_j ; writes planar f32 ----
__global__ void carry_kernel() {
    int idx = blockIdx.x * blockDim.x + threadIdx.x;   // CH*N/2 = 16384
    if (idx >= CH * N / 2) return;
    int c  = idx & (CH - 1);
    int n2 = idx >> 9;
    float2 aTf = ((const float2*)d_AbarT)[n2];
    ull aT = pack2(aTf.x, aTf.y);
    ull carry = 0ULL;
#pragma unroll 4
    for (int j = 0; j < NC; j++) {
        ull s = d_S[((size_t)j * 32 + n2) * CH + c];
        float lo, hi; unpack2(carry, lo, hi);
        d_Hf[((size_t)j * N + 2 * n2)     * CH + c] = lo;
        d_Hf[((size_t)j * N + 2 * n2 + 1) * CH + c] = hi;
        carry = fma2(aT, carry, s);
    }
}

// ---- G2: Y_j = [Toep | W] @ [X_j ; H_j]  (64i x 512c per chunk) ----
__global__ void __launch_bounds__(256) g2_kernel(const float* __restrict__ x,
                                                 float* __restrict__ y) {
    __shared__ float As[32][64];
    __shared__ float Bs[32][128];
    const int j = blockIdx.x, cq = blockIdx.y, tid = threadIdx.x;
    const int ith = tid >> 5, cth = tid & 31;
    const int i0 = ith * 8;

    ull acc[4][4];
#pragma unroll
    for (int p = 0; p < 4; p++)
#pragma unroll
        for (int q = 0; q < 4; q++) acc[p][q] = 0ULL;

    for (int sl = 0; sl < 4; sl++) {
        {   // stage As
            const float4* src = (const float4*)(d_G2A + sl * 32 * 64);
            float4* dst = (float4*)&As[0][0];
            dst[tid] = src[tid];
            dst[tid + 256] = src[tid + 256];
        }
#pragma unroll
        for (int u = 0; u < 4; u++) {   // stage Bs: k<64 from x, k>=64 from Hf
            int e = tid + u * 256;
            int r = e >> 5, fc = e & 31;
            int kg = sl * 32 + r;
            const float* src = (kg < T)
                ? (x    + ((size_t)(j * T + kg)      * CH + cq * 128))
                : (d_Hf + ((size_t)(j * N + kg - T)  * CH + cq * 128));
            ((float4*)&Bs[r][0])[fc] = *((const float4*)src + fc);
        }
        __syncthreads();
#pragma unroll 8
        for (int r = 0; r < 32; r++) {
            float4 a0 = *(const float4*)&As[r][i0];
            float4 a1 = *(const float4*)&As[r][i0 + 4];
            ull a2[4] = { pack2(a0.x, a0.y), pack2(a0.z, a0.w),
                          pack2(a1.x, a1.y), pack2(a1.z, a1.w) };
            float b0 = Bs[r][cth], b1 = Bs[r][cth + 32],
                  b2v = Bs[r][cth + 64], b3 = Bs[r][cth + 96];
            ull bd[4] = { pack2(b0, b0), pack2(b1, b1),
                          pack2(b2v, b2v), pack2(b3, b3) };
#pragma unroll
            for (int p = 0; p < 4; p++)
#pragma unroll
                for (int q = 0; q < 4; q++)
                    acc[p][q] = fma2(a2[p], bd[q], acc[p][q]);
        }
        __syncthreads();
    }
    // epilogue: unpack i-pairs, coalesced 128B stores per (row, q)
#pragma unroll
    for (int p = 0; p < 4; p++) {
        size_t row0 = (size_t)(j * T + i0 + 2 * p) * CH + cq * 128 + cth;
#pragma unroll
        for (int q = 0; q < 4; q++) {
            float lo, hi; unpack2(acc[p][q], lo, hi);
            y[row0 + 32 * q]      = lo;
            y[row0 + CH + 32 * q] = hi;
        }
    }
}

extern "C" void kernel_launch(void* const* d_in, const int* in_sizes, int n_in,
                              void* d_out, int out_size) {
    const float* x    = (const float*)d_in[0];
    const float* logA = (const float*)d_in[1];
    const float* B    = (const float*)d_in[2];
    const float* C    = (const float*)d_in[3];
    float* y = (float*)d_out;

    prep0_kernel<<<1, 256>>>(logA, B, C);
    prep1_kernel<<<48, 256>>>();
    g1_kernel<<<dim3(NC, 4), 256>>>(x);
    carry_kernel<<<128, 128>>>();
    g2_kernel<<<dim3(NC, 4), 256>>>(x, y);
}

// round 14
// speedup vs baseline: 1.1401x; 1.0041x over previous
#include <cuda_runtime.h>

#define L   8192
#define CH  512
#define N   64
#define NC  128
#define T   64
typedef unsigned long long ull;

// ---- constants / scratch (no allocation allowed) ----
__device__ float d_A[N];                       // continuous A_n
__device__ float d_CB[N];                      // C_n * Bbar_n
__device__ float d_AbarT[N];                   // Abar_n^T
__device__ float d_K[T];                       // K[d] = sum_n CB_n Abar_n^d
__device__ float d_G1A[T * N];                 // [s][n] = Abar_n^(63-s)
__device__ float d_G2A[(T + N) * T];           // [k][i]: k<64 Toep, k>=64 W
__device__ ull   d_S[(size_t)NC * (N / 2) * CH];   // [j][n2][c] packed pairs
__device__ float d_Hf[(size_t)NC * N * CH];        // [j][n][c] planar carry-in

// ---- packed f32x2 helpers ----
__device__ __forceinline__ ull pack2(float lo, float hi) {
    ull r; asm("mov.b64 %0, {%1, %2};" : "=l"(r) : "f"(lo), "f"(hi)); return r;
}
__device__ __forceinline__ void unpack2(ull v, float& lo, float& hi) {
    asm("mov.b64 {%0, %1}, %2;" : "=f"(lo), "=f"(hi) : "l"(v));
}
__device__ __forceinline__ ull fma2(ull a, ull b, ull c) {
    ull r; asm("fma.rn.f32x2 %0, %1, %2, %3;" : "=l"(r) : "l"(a), "l"(b), "l"(c)); return r;
}

// ---- prep0: per-state params + Toeplitz kernel K[d] ----
__global__ void prep0_kernel(const float* __restrict__ logA,
                             const float* __restrict__ B,
                             const float* __restrict__ C) {
    __shared__ float sA[N], sCB[N], part[T][4];
    const float dt = 1.0f / 4096.0f;
    int tid = threadIdx.x;
    if (tid < N) {
        float A    = -expf(logA[tid]);
        float Abar = expf(A * dt);
        float Bbar = (Abar - 1.0f) * B[tid] / A;
        float cb   = C[tid] * Bbar;
        d_A[tid] = A;  sA[tid] = A;
        d_CB[tid] = cb; sCB[tid] = cb;
        d_AbarT[tid] = expf(A * dt * (float)T);
    }
    __syncthreads();
    int dpos = tid >> 2, p = tid & 3;
    float s = 0.f;
#pragma unroll
    for (int n = p * 16; n < p * 16 + 16; n++)
        s += sCB[n] * expf(sA[n] * dt * (float)dpos);
    part[dpos][p] = s;
    __syncthreads();
    if (tid < T)
        d_K[tid] = (part[tid][0] + part[tid][1]) + (part[tid][2] + part[tid][3]);
}

// ---- prep1: fill G1/G2 A-matrices (transposed [k][i] layout) ----
__global__ void prep1_kernel() {
    int idx = blockIdx.x * blockDim.x + threadIdx.x;
    const float dt = 1.0f / 4096.0f;
    if (idx < T * N) {                    // d_G1A[s][n] = Abar_n^(63-s)
        int s = idx >> 6, n = idx & 63;
        d_G1A[idx] = expf(d_A[n] * dt * (float)(63 - s));
    }
    int j = idx - T * N;
    if (j >= 0 && j < (T + N) * T) {      // d_G2A[k][i]
        int k = j >> 6, i = j & 63;
        float v;
        if (k < T) v = (i >= k) ? d_K[i - k] : 0.f;
        else {
            int n = k - T;
            v = d_CB[n] * expf(d_A[n] * dt * (float)(i + 1));
        }
        d_G2A[j] = v;
    }
}

// ---- G1: S_j = E @ X_j  (64n x 512c per chunk) ----
__global__ void __launch_bounds__(256) g1_kernel(const float* __restrict__ x) {
    __shared__ float As[32][64];    // 8KB
    __shared__ float Bs[32][128];   // 16KB
    const int j = blockIdx.x, cq = blockIdx.y, tid = threadIdx.x;
    const int ith = tid >> 5, cth = tid & 31;
    const int i0 = ith * 8;

    ull acc[4][4];
#pragma unroll
    for (int p = 0; p < 4; p++)
#pragma unroll
        for (int q = 0; q < 4; q++) acc[p][q] = 0ULL;

    for (int sl = 0; sl < 2; sl++) {
        {   // stage As (2048 f32)
            const float4* src = (const float4*)(d_G1A + sl * 32 * 64);
            float4* dst = (float4*)&As[0][0];
            dst[tid] = src[tid];
            dst[tid + 256] = src[tid + 256];
        }
#pragma unroll
        for (int u = 0; u < 4; u++) {   // stage Bs (32 rows x 128c)
            int e = tid + u * 256;
            int r = e >> 5, fc = e & 31;
            int kg = sl * 32 + r;
            ((float4*)&Bs[r][0])[fc] =
                *((const float4*)(x + ((size_t)(j * T + kg) * CH + cq * 128)) + fc);
        }
        __syncthreads();
#pragma unroll 8
        for (int r = 0; r < 32; r++) {
            float4 a0 = *(const float4*)&As[r][i0];
            float4 a1 = *(const float4*)&As[r][i0 + 4];
            ull a2[4] = { pack2(a0.x, a0.y), pack2(a0.z, a0.w),
                          pack2(a1.x, a1.y), pack2(a1.z, a1.w) };
            float b0 = Bs[r][cth], b1 = Bs[r][cth + 32],
                  b2v = Bs[r][cth + 64], b3 = Bs[r][cth + 96];
            ull bd[4] = { pack2(b0, b0), pack2(b1, b1),
                          pack2(b2v, b2v), pack2(b3, b3) };
#pragma unroll
            for (int p = 0; p < 4; p++)
#pragma unroll
                for (int q = 0; q < 4; q++)
                    acc[p][q] = fma2(a2[p], bd[q], acc[p][q]);
        }
        __syncthreads();
    }
    // store S (pairs (2n2, 2n2+1) in one ull)
    ull* Sp = d_S + (size_t)j * 32 * CH;
#pragma unroll
    for (int p = 0; p < 4; p++)
#pragma unroll
        for (int q = 0; q < 4; q++)
            Sp[(size_t)(i0 / 2 + p) * CH + cq * 128 + cth + 32 * q] = acc[p][q];
}

// ---- carry: H_{j+1} = AbarT (.) H_j + S_j ; writes planar f32 ----
__global__ void carry_kernel() {
    int idx = blockIdx.x * blockDim.x + threadIdx.x;   // CH*N/2 = 16384
    if (idx >= CH * N / 2) return;
    int c  = idx & (CH - 1);
    int n2 = idx >> 9;
    float2 aTf = ((const float2*)d_AbarT)[n2];
    ull aT = pack2(aTf.x, aTf.y);
    ull carry = 0ULL;
#pragma unroll 4
    for (int j = 0; j < NC; j++) {
        ull s = d_S[((size_t)j * 32 + n2) * CH + c];
        float lo, hi; unpack2(carry, lo, hi);
        d_Hf[((size_t)j * N + 2 * n2)     * CH + c] = lo;
        d_Hf[((size_t)j * N + 2 * n2 + 1) * CH + c] = hi;
        carry = fma2(aT, carry, s);
    }
}

// ---- G2: Y_j = [Toep | W] @ [X_j ; H_j]  (64i x 512c per chunk) ----
__global__ void __launch_bounds__(256) g2_kernel(const float* __restrict__ x,
                                                 float* __restrict__ y) {
    __shared__ float As[32][64];
    __shared__ float Bs[32][128];
    const int j = blockIdx.x, cq = blockIdx.y, tid = threadIdx.x;
    const int ith = tid >> 5, cth = tid & 31;
    const int i0 = ith * 8;

    ull acc[4][4];
#pragma unroll
    for (int p = 0; p < 4; p++)
#pragma unroll
        for (int q = 0; q < 4; q++) acc[p][q] = 0ULL;

    for (int sl = 0; sl < 4; sl++) {
        {   // stage As
            const float4* src = (const float4*)(d_G2A + sl * 32 * 64);
            float4* dst = (float4*)&As[0][0];
            dst[tid] = src[tid];
            dst[tid + 256] = src[tid + 256];
        }
#pragma unroll
        for (int u = 0; u < 4; u++) {   // stage Bs: k<64 from x, k>=64 from Hf
            int e = tid + u * 256;
            int r = e >> 5, fc = e & 31;
            int kg = sl * 32 + r;
            const float* src = (kg < T)
                ? (x    + ((size_t)(j * T + kg)      * CH + cq * 128))
                : (d_Hf + ((size_t)(j * N + kg - T)  * CH + cq * 128));
            ((float4*)&Bs[r][0])[fc] = *((const float4*)src + fc);
        }
        __syncthreads();
#pragma unroll 8
        for (int r = 0; r < 32; r++) {
            float4 a0 = *(const float4*)&As[r][i0];
            float4 a1 = *(const float4*)&As[r][i0 + 4];
            ull a2[4] = { pack2(a0.x, a0.y), pack2(a0.z, a0.w),
                          pack2(a1.x, a1.y), pack2(a1.z, a1.w) };
            float b0 = Bs[r][cth], b1 = Bs[r][cth + 32],
                  b2v = Bs[r][cth + 64], b3 = Bs[r][cth + 96];
            ull bd[4] = { pack2(b0, b0), pack2(b1, b1),
                          pack2(b2v, b2v), pack2(b3, b3) };
#pragma unroll
            for (int p = 0; p < 4; p++)
#pragma unroll
                for (int q = 0; q < 4; q++)
                    acc[p][q] = fma2(a2[p], bd[q], acc[p][q]);
        }
        __syncthreads();
    }
    // epilogue: unpack i-pairs, coalesced 128B stores per (row, q)
#pragma unroll
    for (int p = 0; p < 4; p++) {
        size_t row0 = (size_t)(j * T + i0 + 2 * p) * CH + cq * 128 + cth;
#pragma unroll
        for (int q = 0; q < 4; q++) {
            float lo, hi; unpack2(acc[p][q], lo, hi);
            y[row0 + 32 * q]      = lo;
            y[row0 + CH + 32 * q] = hi;
        }
    }
}

extern "C" void kernel_launch(void* const* d_in, const int* in_sizes, int n_in,
                              void* d_out, int out_size) {
    const float* x    = (const float*)d_in[0];
    const float* logA = (const float*)d_in[1];
    const float* B    = (const float*)d_in[2];
    const float* C    = (const float*)d_in[3];
    float* y = (float*)d_out;

    prep0_kernel<<<1, 256>>>(logA, B, C);
    prep1_kernel<<<48, 256>>>();
    g1_kernel<<<dim3(NC, 4), 256>>>(x);
    carry_kernel<<<128, 128>>>();
    g2_kernel<<<dim3(NC, 4), 256>>>(x, y);
}